// round 11
// baseline (speedup 1.0000x reference)
#include <cuda_runtime.h>

// Round 11: round 10 + in-conv merge of ic-half partials.
//  - yT halved to 6KB (ih0 stores, barrier, ih1 read-add-store; deterministic),
//    assembly reads 3 float4/task instead of 6.
//  - smem 42 -> ~36KB, launch_bounds(256,6) -> 6 blocks/SM.
//  - conv unroll 4 to fit 40-reg budget.
namespace {

constexpr int GRID_H = 13;
constexpr int GRID_W = 3;
constexpr int G      = GRID_H * GRID_W;   // 39
constexpr int ENC    = 128;
constexpr int TS     = 16;
constexpr int C31    = 16;
constexpr int C11    = 32;
constexpr int SOCD   = 64;
constexpr int KN     = 32;
constexpr int U      = 4;                 // batches per block
constexpr int FPITCH = 129;
constexpr int MAXJ   = U * KN;
constexpr int FCD    = 160;

__device__ __align__(16) float wT[3 * ENC * C31];     // [kh][ic][oc16]
__device__ __align__(16) float fcwT[FCD * SOCD];      // [f][o]

__device__ __forceinline__ float lrelu(float x) { return x > 0.0f ? x : 0.1f * x; }

__global__ void prep_kernel(const float* __restrict__ w31,
                            const float* __restrict__ fcw)
{
    int i = blockIdx.x * 256 + threadIdx.x;
    if (i < 3 * ENC * C31) {
        int kh = i >> 11;
        int r  = i & 2047;
        int ic = r >> 4, oc = r & 15;
        wT[i] = w31[(oc * ENC + ic) * 3 + kh];
    }
    if (i < FCD * SOCD) {
        int f = i >> 6, o = i & 63;
        fcwT[i] = fcw[o * FCD + f];
    }
}

__global__ __launch_bounds__(256, 6)
void csp_kernel(const float* __restrict__ enc,   // [N_VEH,128,16]
                const int*   __restrict__ nb,    // [B,32]
                const int*   __restrict__ gp,    // [N_VEH,2]
                const float* __restrict__ b31,   // [16]
                const float* __restrict__ w11,   // [32,16]
                const float* __restrict__ b11,   // [32]
                const float* __restrict__ fcb,   // [64]
                float*       __restrict__ out,   // [B,64]
                int batch)
{
    __shared__ __align__(16) float featC[32 * FPITCH];   // 16512B; later red[4][64][4]
    __shared__ __align__(16) float yT[32 * 3 * C31];     // 6144B; later p[160][4]
    __shared__ __align__(16) float a1[U * G * C31];      // 9984B; winner ints at start
    __shared__ __align__(16) float w11s[C31 * C11];      // [ic][oc]
    __shared__ __align__(16) float b31s[C31];
    __shared__ float b11s[C11];
    __shared__ int   jOf[U * G];
    __shared__ int   vehG[MAXJ];
    __shared__ int   totCnt;

    const int b0  = blockIdx.x * U;
    const int tid = threadIdx.x;
    const int wid = tid >> 5;
    const int lan = tid & 31;

    // ---- stage small weights / init ----
    for (int i = tid; i < C31 * C11; i += 256) {
        int ic = i >> 5, oc = i & 31;
        w11s[i] = __ldg(w11 + oc * C31 + ic);
    }
    if (tid < C31) b31s[tid] = __ldg(b31 + tid);
    if (tid < C11) b11s[tid] = __ldg(b11 + tid);
    if (tid < U * G) jOf[tid] = -1;
    if (tid == 0) totCnt = 0;
    int* winner = (int*)a1;
    if (tid < U * G) winner[tid] = -1;
    __syncthreads();

    // ---- winners per cell ----
    if (tid < U * KN) {
        int u = tid >> 5, k = tid & 31;
        int b = b0 + u;
        if (b < batch) {
            int v = nb[b * KN + k];
            int x = __ldg(gp + 2 * v), yy = __ldg(gp + 2 * v + 1);
            if (x >= 0 && x < GRID_H && yy >= 0 && yy < GRID_W)
                atomicMax(&winner[u * G + x * GRID_W + yy], k);
        }
    }
    __syncthreads();
    if (tid < U * G) {
        int w = winner[tid];
        if (w >= 0) {
            int u = tid / G;
            int v = nb[(b0 + u) * KN + w];
            int j = atomicAdd(&totCnt, 1);
            jOf[tid] = j;
            vehG[j]  = v;
        }
    }
    __syncthreads();
    const int tot    = totCnt;
    const int ntiles = (tot + 31) >> 5;

    // ---- init a1 = bias (float4; winner scratch dead) ----
    {
        const float4* bv = (const float4*)b31s;
        float4* a1v = (float4*)a1;
        for (int e = tid; e < U * G * 4; e += 256)
            a1v[e] = bv[e & 3];
    }
    __syncthreads();

    // ---- tiles: gather -> conv3x1 (8 tasks, in-conv ih merge) -> accumulate a1 ----
    for (int t = 0; t < ntiles; ++t) {
        const int  jBase = t << 5;
        const int  nT    = min(32, tot - jBase);
        const bool last  = (t == ntiles - 1);

        for (int i = tid; i < (nT << 7); i += 256) {
            int s = i >> 7, ic = i & 127;
            int v = vehG[jBase + s];
            featC[s * FPITCH + ic] =
                __ldg(enc + (size_t)v * (ENC * TS) + ic * TS + (TS - 1));
        }
        __syncthreads();

        // conv: warp = (ocg, ih). lane = slot. 3 kh-accumulators, one feat pass.
        {
            const int ocg = wid & 3;
            const int ih  = wid >> 2;             // ic half: [64*ih, 64*ih+64)
            const float*  fr = featC + lan * FPITCH + (ih << 6);
            const float4* w0 = (const float4*)wT + ((ih << 6) << 2) + ocg;          // kh=0
            const float4* w1 = (const float4*)wT + 512 + ((ih << 6) << 2) + ocg;    // kh=1
            const float4* w2 = (const float4*)wT + 1024 + ((ih << 6) << 2) + ocg;   // kh=2
            float4 ac0 = make_float4(0.f, 0.f, 0.f, 0.f);
            float4 ac1 = make_float4(0.f, 0.f, 0.f, 0.f);
            float4 ac2 = make_float4(0.f, 0.f, 0.f, 0.f);
            #pragma unroll 4
            for (int j = 0; j < 64; ++j) {
                float  f  = fr[j];
                float4 v0 = __ldg(w0 + (j << 2));   // uniform across lanes
                float4 v1 = __ldg(w1 + (j << 2));
                float4 v2 = __ldg(w2 + (j << 2));
                ac0.x += f * v0.x; ac0.y += f * v0.y; ac0.z += f * v0.z; ac0.w += f * v0.w;
                ac1.x += f * v1.x; ac1.y += f * v1.y; ac1.z += f * v1.z; ac1.w += f * v1.w;
                ac2.x += f * v2.x; ac2.y += f * v2.y; ac2.z += f * v2.z; ac2.w += f * v2.w;
            }
            float4* yb = (float4*)yT + ((lan * 3) << 2) + ocg;
            // ih=0 stores, then ih=1 accumulates on top (fixed order -> deterministic)
            if (ih == 0 && lan < nT) {
                yb[0] = ac0; yb[4] = ac1; yb[8] = ac2;
            }
            __syncthreads();
            if (ih == 1 && lan < nT) {
                float4 t0 = yb[0], t1 = yb[4], t2 = yb[8];
                t0.x += ac0.x; t0.y += ac0.y; t0.z += ac0.z; t0.w += ac0.w;
                t1.x += ac1.x; t1.y += ac1.y; t1.z += ac1.z; t1.w += ac1.w;
                t2.x += ac2.x; t2.y += ac2.y; t2.z += ac2.z; t2.w += ac2.w;
                yb[0] = t0; yb[4] = t1; yb[8] = t2;
            }
        }
        __syncthreads();

        // accumulate tile partials into a1 (float4; fixed ownership -> deterministic)
        for (int e = tid; e < U * G * 4; e += 256) {
            int u   = e / (G * 4);
            int r   = e - u * (G * 4);
            int pos = r >> 2, g = r & 3;
            int h = pos / 3, w = pos - h * 3;
            float4 val = ((float4*)a1)[e];
            #pragma unroll
            for (int dh = -1; dh <= 1; ++dh) {
                int hh = h + dh;
                if ((unsigned)hh < (unsigned)GRID_H) {
                    int j = jOf[u * G + hh * 3 + w];
                    int s = j - jBase;
                    if (s >= 0 && s < nT) {
                        float4 yv = ((const float4*)yT)[((s * 3 + dh + 1) << 2) + g];
                        val.x += yv.x; val.y += yv.y; val.z += yv.z; val.w += yv.w;
                    }
                }
            }
            if (last) {
                val.x = lrelu(val.x); val.y = lrelu(val.y);
                val.z = lrelu(val.z); val.w = lrelu(val.w);
            }
            ((float4*)a1)[e] = val;
        }
        __syncthreads();
    }
    if (ntiles == 0) {
        for (int e = tid; e < U * G * 4; e += 256) {
            float4 v = ((float4*)a1)[e];
            v.x = lrelu(v.x); v.y = lrelu(v.y); v.z = lrelu(v.z); v.w = lrelu(v.w);
            ((float4*)a1)[e] = v;
        }
        __syncthreads();
    }

    // ---- conv1x1 + lrelu + 3x3/3 maxpool. warp-task=(u,ph), lane=oc2; float4 a1 reads ----
    float* const p = yT;   // p[f][u], f = oc2*5+ph; yT dead
    for (int wt = wid; wt < U * 5; wt += 8) {
        int u = wt / 5, ph = wt - u * 5;
        float wr[16];
        #pragma unroll
        for (int ic = 0; ic < 16; ++ic) wr[ic] = w11s[(ic << 5) + lan];
        float bias = b11s[lan];
        float m = -3.4e38f;
        int h1 = min(3 * ph + 3, GRID_H);
        for (int h = 3 * ph; h < h1; ++h) {
            #pragma unroll
            for (int w = 0; w < 3; ++w) {
                const float4* ar = (const float4*)(a1 + u * (G * C31) + ((h * 3 + w) << 4));
                float4 q0 = ar[0], q1 = ar[1], q2 = ar[2], q3 = ar[3];
                float s = bias
                    + q0.x * wr[0]  + q0.y * wr[1]  + q0.z * wr[2]  + q0.w * wr[3]
                    + q1.x * wr[4]  + q1.y * wr[5]  + q1.z * wr[6]  + q1.w * wr[7]
                    + q2.x * wr[8]  + q2.y * wr[9]  + q2.z * wr[10] + q2.w * wr[11]
                    + q3.x * wr[12] + q3.y * wr[13] + q3.z * wr[14] + q3.w * wr[15];
                m = fmaxf(m, lrelu(s));
            }
        }
        p[((lan * 5 + ph) << 2) + u] = m;
    }
    __syncthreads();

    // ---- FC 160->64 cooperative: warp=(o-half, f-quarter) ----
    float* const red = featC;                    // red[fq][o][u]; featC dead
    {
        int orr = wid & 1, fq = wid >> 1;
        int o = (orr << 5) + lan;
        float a0 = 0.f, s1 = 0.f, a2 = 0.f, a3 = 0.f;
        int f0 = fq * 40;
        #pragma unroll 8
        for (int f = f0; f < f0 + 40; ++f) {
            float  wv = __ldg(fcwT + (f << 6) + o);        // 1 line / warp
            float4 pv = *(const float4*)(p + (f << 2));    // uniform
            a0 += wv * pv.x; s1 += wv * pv.y;
            a2 += wv * pv.z; a3 += wv * pv.w;
        }
        *(float4*)(red + ((fq << 6) + o) * 4) = make_float4(a0, s1, a2, a3);
    }
    __syncthreads();
    {
        int u = tid >> 6, o = tid & 63;
        int b = b0 + u;
        if (b < batch) {
            float acc = __ldg(fcb + o);
            #pragma unroll
            for (int fq = 0; fq < 4; ++fq)
                acc += red[((fq << 6) + o) * 4 + u];
            out[b * SOCD + o] = lrelu(acc);
        }
    }
}

} // namespace

extern "C" void kernel_launch(void* const* d_in, const int* in_sizes, int n_in,
                              void* d_out, int out_size)
{
    const float* enc = (const float*)d_in[0];
    const int*   nb  = (const int*)  d_in[1];
    const int*   gp  = (const int*)  d_in[2];
    const float* w31 = (const float*)d_in[3];
    const float* b31 = (const float*)d_in[4];
    const float* w11 = (const float*)d_in[5];
    const float* b11 = (const float*)d_in[6];
    const float* fcw = (const float*)d_in[7];
    const float* fcb = (const float*)d_in[8];
    float* out = (float*)d_out;

    const int batch = in_sizes[1] / KN;   // 8192

    prep_kernel<<<(FCD * SOCD + 255) / 256, 256>>>(w31, fcw);
    csp_kernel<<<(batch + U - 1) / U, 256>>>(enc, nb, gp, b31, w11, b11, fcb, out, batch);
}

// round 12
// speedup vs baseline: 1.1253x; 1.1253x over previous
#include <cuda_runtime.h>

// Round 12: round-10 base + exact output-sparsity in pool/assembly.
//  - active positions = those with >=1 occupied column-neighbor (~41%).
//    Assembly runs only over the active list; inactive a1 never written/read.
//  - pool substitutes precomputed c0 = lrelu(w11 . lrelu(b31) + b11) for
//    inactive cells (warp-uniform branch); w11 column hoisted per warp.
//  - conv / gather / FC identical to round 10 (166us best).
namespace {

constexpr int GRID_H = 13;
constexpr int GRID_W = 3;
constexpr int G      = GRID_H * GRID_W;   // 39
constexpr int ENC    = 128;
constexpr int TS     = 16;
constexpr int C31    = 16;
constexpr int C11    = 32;
constexpr int SOCD   = 64;
constexpr int KN     = 32;
constexpr int U      = 4;                 // batches per block
constexpr int FPITCH = 129;
constexpr int MAXJ   = U * KN;
constexpr int FCD    = 160;

__device__ __align__(16) float wT[3 * ENC * C31];     // [kh][ic][oc16]
__device__ __align__(16) float fcwT[FCD * SOCD];      // [f][o]
__device__ __align__(16) float c0g[C11];              // lrelu(w11.lrelu(b31)+b11)

__device__ __forceinline__ float lrelu(float x) { return x > 0.0f ? x : 0.1f * x; }

__global__ void prep_kernel(const float* __restrict__ w31,
                            const float* __restrict__ fcw,
                            const float* __restrict__ b31,
                            const float* __restrict__ w11,
                            const float* __restrict__ b11)
{
    int i = blockIdx.x * 256 + threadIdx.x;
    if (i < 3 * ENC * C31) {
        int kh = i >> 11;
        int r  = i & 2047;
        int ic = r >> 4, oc = r & 15;
        wT[i] = w31[(oc * ENC + ic) * 3 + kh];
    }
    if (i < FCD * SOCD) {
        int f = i >> 6, o = i & 63;
        fcwT[i] = fcw[o * FCD + f];
    }
    if (i < C11) {                       // c0 for empty-neighborhood positions
        float s = b11[i];
        for (int ic = 0; ic < C31; ++ic)
            s += w11[i * C31 + ic] * lrelu(b31[ic]);
        c0g[i] = lrelu(s);
    }
}

__global__ __launch_bounds__(256, 5)
void csp_kernel(const float* __restrict__ enc,   // [N_VEH,128,16]
                const int*   __restrict__ nb,    // [B,32]
                const int*   __restrict__ gp,    // [N_VEH,2]
                const float* __restrict__ b31,   // [16]
                const float* __restrict__ w11,   // [32,16]
                const float* __restrict__ b11,   // [32]
                const float* __restrict__ fcb,   // [64]
                float*       __restrict__ out,   // [B,64]
                int batch)
{
    __shared__ __align__(16) float featC[32 * FPITCH];   // 16512B; later red[4][64][4]
    __shared__ __align__(16) float yT[2 * 32 * 3 * C31]; // 12288B; later p[160][4]
    __shared__ __align__(16) float a1[U * G * C31];      // 9984B; winner ints at start
    __shared__ __align__(16) float w11s[C31 * C11];      // [ic][oc]
    __shared__ __align__(16) float b31s[C31];
    __shared__ float b11s[C11];
    __shared__ float c0s[C11];
    __shared__ int   jOf[U * G];
    __shared__ int   actFlag[U * G];
    __shared__ int   actList[U * G];
    __shared__ int   vehG[MAXJ];
    __shared__ int   totCnt;
    __shared__ int   nActCnt;

    const int b0  = blockIdx.x * U;
    const int tid = threadIdx.x;
    const int wid = tid >> 5;
    const int lan = tid & 31;

    // ---- stage small weights / init ----
    for (int i = tid; i < C31 * C11; i += 256) {
        int ic = i >> 5, oc = i & 31;
        w11s[i] = __ldg(w11 + oc * C31 + ic);
    }
    if (tid < C31) b31s[tid] = __ldg(b31 + tid);
    if (tid < C11) { b11s[tid] = __ldg(b11 + tid); c0s[tid] = c0g[tid]; }
    if (tid < U * G) jOf[tid] = -1;
    if (tid == 0) { totCnt = 0; nActCnt = 0; }
    int* winner = (int*)a1;
    if (tid < U * G) winner[tid] = -1;
    __syncthreads();

    // ---- winners per cell ----
    if (tid < U * KN) {
        int u = tid >> 5, k = tid & 31;
        int b = b0 + u;
        if (b < batch) {
            int v = nb[b * KN + k];
            int x = __ldg(gp + 2 * v), yy = __ldg(gp + 2 * v + 1);
            if (x >= 0 && x < GRID_H && yy >= 0 && yy < GRID_W)
                atomicMax(&winner[u * G + x * GRID_W + yy], k);
        }
    }
    __syncthreads();
    if (tid < U * G) {
        int w = winner[tid];
        if (w >= 0) {
            int u = tid / G;
            int v = nb[(b0 + u) * KN + w];
            int j = atomicAdd(&totCnt, 1);
            jOf[tid] = j;
            vehG[j]  = v;
        }
    }
    __syncthreads();

    // ---- active positions: any occupied column-neighbor ----
    if (tid < U * G) {
        int pos = tid % G;
        int h   = pos / 3;
        bool a = jOf[tid] >= 0;
        if (h > 0)          a |= jOf[tid - 3] >= 0;
        if (h < GRID_H - 1) a |= jOf[tid + 3] >= 0;
        actFlag[tid] = a ? 1 : 0;
        if (a) {
            int s = atomicAdd(&nActCnt, 1);
            actList[s] = tid;
        }
    }
    __syncthreads();
    const int tot    = totCnt;
    const int nAct   = nActCnt;
    const int ntiles = (tot + 31) >> 5;

    // ---- tiles: gather -> conv3x1 (round-10) -> sparse assembly ----
    for (int t = 0; t < ntiles; ++t) {
        const int  jBase = t << 5;
        const int  nT    = min(32, tot - jBase);
        const bool last  = (t == ntiles - 1);

        for (int i = tid; i < (nT << 7); i += 256) {
            int s = i >> 7, ic = i & 127;
            int v = vehG[jBase + s];
            featC[s * FPITCH + ic] =
                __ldg(enc + (size_t)v * (ENC * TS) + ic * TS + (TS - 1));
        }
        __syncthreads();

        // conv: warp = (ocg, ih). lane = slot. 3 kh-accumulators, one feat pass.
        {
            const int ocg = wid & 3;
            const int ih  = wid >> 2;             // ic half: [64*ih, 64*ih+64)
            const float*  fr = featC + lan * FPITCH + (ih << 6);
            const float4* w0 = (const float4*)wT + ((ih << 6) << 2) + ocg;          // kh=0
            const float4* w1 = (const float4*)wT + 512 + ((ih << 6) << 2) + ocg;    // kh=1
            const float4* w2 = (const float4*)wT + 1024 + ((ih << 6) << 2) + ocg;   // kh=2
            float4 ac0 = make_float4(0.f, 0.f, 0.f, 0.f);
            float4 ac1 = make_float4(0.f, 0.f, 0.f, 0.f);
            float4 ac2 = make_float4(0.f, 0.f, 0.f, 0.f);
            #pragma unroll 8
            for (int j = 0; j < 64; ++j) {
                float  f  = fr[j];
                float4 v0 = __ldg(w0 + (j << 2));   // uniform across lanes
                float4 v1 = __ldg(w1 + (j << 2));
                float4 v2 = __ldg(w2 + (j << 2));
                ac0.x += f * v0.x; ac0.y += f * v0.y; ac0.z += f * v0.z; ac0.w += f * v0.w;
                ac1.x += f * v1.x; ac1.y += f * v1.y; ac1.z += f * v1.z; ac1.w += f * v1.w;
                ac2.x += f * v2.x; ac2.y += f * v2.y; ac2.z += f * v2.z; ac2.w += f * v2.w;
            }
            if (lan < nT) {
                float4* yb = (float4*)yT + (((ih << 5) + lan) * 3 << 2) + ocg;
                yb[0] = ac0; yb[4] = ac1; yb[8] = ac2;
            }
        }
        __syncthreads();

        // sparse assembly: only active positions. task a = (active idx)*4 + g.
        for (int a = tid; a < (nAct << 2); a += 256) {
            int e = actList[a >> 2];                 // u*G + pos
            int g = a & 3;
            int pos = e % G;
            int h   = pos / 3;
            float4 val;
            if (t == 0) val = ((const float4*)b31s)[g];
            else        val = ((float4*)a1)[(e << 2) + g];
            #pragma unroll
            for (int dh = -1; dh <= 1; ++dh) {
                int hh = h + dh;
                if ((unsigned)hh < (unsigned)GRID_H) {
                    int j = jOf[e + dh * 3];
                    int s = j - jBase;
                    if (s >= 0 && s < nT) {
                        int kh = dh + 1;
                        float4 y0 = ((const float4*)yT)[((      s) * 3 + kh) * 4 + g];
                        float4 y1 = ((const float4*)yT)[((32 +  s) * 3 + kh) * 4 + g];
                        val.x += y0.x + y1.x; val.y += y0.y + y1.y;
                        val.z += y0.z + y1.z; val.w += y0.w + y1.w;
                    }
                }
            }
            if (last) {
                val.x = lrelu(val.x); val.y = lrelu(val.y);
                val.z = lrelu(val.z); val.w = lrelu(val.w);
            }
            ((float4*)a1)[(e << 2) + g] = val;
        }
        __syncthreads();
    }

    // ---- conv1x1 + lrelu + 3x3/3 maxpool with c0 shortcut.
    //      warp-task=(u,ph), lane=oc2; branch on actFlag is warp-uniform. ----
    float* const p = yT;   // p[f][u], f = oc2*5+ph; yT dead
    {
        float wr[16];                              // hoisted: same for all tasks
        #pragma unroll
        for (int ic = 0; ic < 16; ++ic) wr[ic] = w11s[(ic << 5) + lan];
        const float bias = b11s[lan];
        const float c0v  = c0s[lan];
        for (int wt = wid; wt < U * 5; wt += 8) {
            int u = wt / 5, ph = wt - u * 5;
            float m = -3.4e38f;
            int e0 = u * G + 3 * ph * 3;
            int h1 = min(3 * ph + 3, GRID_H);
            for (int h = 3 * ph; h < h1; ++h) {
                #pragma unroll
                for (int w = 0; w < 3; ++w) {
                    int e = u * G + h * 3 + w;
                    float s;
                    if (actFlag[e]) {              // uniform across warp
                        const float4* ar = (const float4*)(a1 + (e << 4));
                        float4 q0 = ar[0], q1 = ar[1], q2 = ar[2], q3 = ar[3];
                        s = bias
                            + q0.x * wr[0]  + q0.y * wr[1]  + q0.z * wr[2]  + q0.w * wr[3]
                            + q1.x * wr[4]  + q1.y * wr[5]  + q1.z * wr[6]  + q1.w * wr[7]
                            + q2.x * wr[8]  + q2.y * wr[9]  + q2.z * wr[10] + q2.w * wr[11]
                            + q3.x * wr[12] + q3.y * wr[13] + q3.z * wr[14] + q3.w * wr[15];
                        s = lrelu(s);
                    } else {
                        s = c0v;
                    }
                    m = fmaxf(m, s);
                }
            }
            (void)e0;
            p[((lan * 5 + ph) << 2) + u] = m;
        }
    }
    __syncthreads();

    // ---- FC 160->64 cooperative: warp=(o-half, f-quarter) ----
    float* const red = featC;                    // red[fq][o][u]; featC dead
    {
        int orr = wid & 1, fq = wid >> 1;
        int o = (orr << 5) + lan;
        float a0 = 0.f, s1 = 0.f, a2 = 0.f, a3 = 0.f;
        int f0 = fq * 40;
        #pragma unroll 8
        for (int f = f0; f < f0 + 40; ++f) {
            float  wv = __ldg(fcwT + (f << 6) + o);        // 1 line / warp
            float4 pv = *(const float4*)(p + (f << 2));    // uniform
            a0 += wv * pv.x; s1 += wv * pv.y;
            a2 += wv * pv.z; a3 += wv * pv.w;
        }
        *(float4*)(red + ((fq << 6) + o) * 4) = make_float4(a0, s1, a2, a3);
    }
    __syncthreads();
    {
        int u = tid >> 6, o = tid & 63;
        int b = b0 + u;
        if (b < batch) {
            float acc = __ldg(fcb + o);
            #pragma unroll
            for (int fq = 0; fq < 4; ++fq)
                acc += red[((fq << 6) + o) * 4 + u];
            out[b * SOCD + o] = lrelu(acc);
        }
    }
}

} // namespace

extern "C" void kernel_launch(void* const* d_in, const int* in_sizes, int n_in,
                              void* d_out, int out_size)
{
    const float* enc = (const float*)d_in[0];
    const int*   nb  = (const int*)  d_in[1];
    const int*   gp  = (const int*)  d_in[2];
    const float* w31 = (const float*)d_in[3];
    const float* b31 = (const float*)d_in[4];
    const float* w11 = (const float*)d_in[5];
    const float* b11 = (const float*)d_in[6];
    const float* fcw = (const float*)d_in[7];
    const float* fcb = (const float*)d_in[8];
    float* out = (float*)d_out;

    const int batch = in_sizes[1] / KN;   // 8192

    prep_kernel<<<(FCD * SOCD + 255) / 256, 256>>>(w31, fcw, b31, w11, b11);
    csp_kernel<<<(batch + U - 1) / U, 256>>>(enc, nb, gp, b31, w11, b11, fcb, out, batch);
}

// round 13
// speedup vs baseline: 1.1388x; 1.0120x over previous
#include <cuda_runtime.h>

// Round 13: round-12 structure with U=8 batches/block (dynamic smem ~55KB).
//  - halves per-batch fixed costs: barriers, weight staging, winner setup,
//    pool hoist, FC; doubles gather MLP.
//  - conv3x1 / sparse assembly / c0-pool / cooperative FC logic unchanged.
namespace {

constexpr int GRID_H = 13;
constexpr int GRID_W = 3;
constexpr int G      = GRID_H * GRID_W;   // 39
constexpr int ENC    = 128;
constexpr int TS     = 16;
constexpr int C31    = 16;
constexpr int C11    = 32;
constexpr int SOCD   = 64;
constexpr int KN     = 32;
constexpr int U      = 8;                 // batches per block
constexpr int FPITCH = 129;
constexpr int MAXJ   = U * KN;            // 256
constexpr int FCD    = 160;

// dynamic smem layout (float offsets)
constexpr int OFF_FEATC = 0;                       // 32*129 = 4128; later red[4][64][8]
constexpr int OFF_YT    = OFF_FEATC + 32 * FPITCH; // 3072 (2 ih halves); later p[160][8]
constexpr int OFF_A1    = OFF_YT + 2 * 32 * 3 * C31;   // 4992 = U*G*C31
constexpr int OFF_W11S  = OFF_A1 + U * G * C31;    // 512
constexpr int OFF_B31S  = OFF_W11S + C31 * C11;    // 16
constexpr int OFF_B11S  = OFF_B31S + C31;          // 32
constexpr int OFF_C0S   = OFF_B11S + C11;          // 32
constexpr int OFF_INT   = OFF_C0S + C11;           // ints from here
constexpr int NI_JOF    = U * G;                   // 312
constexpr int NI_FLAG   = U * G;
constexpr int NI_LIST   = U * G;
constexpr int SMEM_BYTES = OFF_INT * 4 + (3 * NI_JOF + MAXJ + 2) * 4 + 64;

__device__ __align__(16) float wT[3 * ENC * C31];     // [kh][ic][oc16]
__device__ __align__(16) float fcwT[FCD * SOCD];      // [f][o]
__device__ __align__(16) float c0g[C11];              // lrelu(w11.lrelu(b31)+b11)

__device__ __forceinline__ float lrelu(float x) { return x > 0.0f ? x : 0.1f * x; }

__global__ void prep_kernel(const float* __restrict__ w31,
                            const float* __restrict__ fcw,
                            const float* __restrict__ b31,
                            const float* __restrict__ w11,
                            const float* __restrict__ b11)
{
    int i = blockIdx.x * 256 + threadIdx.x;
    if (i < 3 * ENC * C31) {
        int kh = i >> 11;
        int r  = i & 2047;
        int ic = r >> 4, oc = r & 15;
        wT[i] = w31[(oc * ENC + ic) * 3 + kh];
    }
    if (i < FCD * SOCD) {
        int f = i >> 6, o = i & 63;
        fcwT[i] = fcw[o * FCD + f];
    }
    if (i < C11) {
        float s = b11[i];
        for (int ic = 0; ic < C31; ++ic)
            s += w11[i * C31 + ic] * lrelu(b31[ic]);
        c0g[i] = lrelu(s);
    }
}

__global__ __launch_bounds__(256, 4)
void csp_kernel(const float* __restrict__ enc,   // [N_VEH,128,16]
                const int*   __restrict__ nb,    // [B,32]
                const int*   __restrict__ gp,    // [N_VEH,2]
                const float* __restrict__ b31,   // [16]
                const float* __restrict__ w11,   // [32,16]
                const float* __restrict__ b11,   // [32]
                const float* __restrict__ fcb,   // [64]
                float*       __restrict__ out,   // [B,64]
                int batch)
{
    extern __shared__ __align__(16) float sm[];
    float* const featC = sm + OFF_FEATC;
    float* const yT    = sm + OFF_YT;
    float* const a1    = sm + OFF_A1;
    float* const w11s  = sm + OFF_W11S;
    float* const b31s  = sm + OFF_B31S;
    float* const b11s  = sm + OFF_B11S;
    float* const c0s   = sm + OFF_C0S;
    int*   const jOf     = (int*)(sm + OFF_INT);
    int*   const actFlag = jOf + NI_JOF;
    int*   const actList = actFlag + NI_FLAG;
    int*   const vehG    = actList + NI_LIST;
    int*   const cnts    = vehG + MAXJ;           // [0]=totCnt [1]=nActCnt

    const int b0  = blockIdx.x * U;
    const int tid = threadIdx.x;
    const int wid = tid >> 5;
    const int lan = tid & 31;

    // ---- stage small weights / init ----
    for (int i = tid; i < C31 * C11; i += 256) {
        int ic = i >> 5, oc = i & 31;
        w11s[i] = __ldg(w11 + oc * C31 + ic);
    }
    if (tid < C31) b31s[tid] = __ldg(b31 + tid);
    if (tid < C11) { b11s[tid] = __ldg(b11 + tid); c0s[tid] = c0g[tid]; }
    for (int i = tid; i < U * G; i += 256) jOf[i] = -1;
    if (tid < 2) cnts[tid] = 0;
    int* winner = (int*)a1;                       // a1 region as winner scratch
    for (int i = tid; i < U * G; i += 256) winner[i] = -1;
    __syncthreads();

    // ---- winners per cell (exactly 256 = U*KN threads) ----
    {
        int u = tid >> 5, k = tid & 31;
        int b = b0 + u;
        if (b < batch) {
            int v = nb[b * KN + k];
            int x = __ldg(gp + 2 * v), yy = __ldg(gp + 2 * v + 1);
            if (x >= 0 && x < GRID_H && yy >= 0 && yy < GRID_W)
                atomicMax(&winner[u * G + x * GRID_W + yy], k);
        }
    }
    __syncthreads();
    for (int i = tid; i < U * G; i += 256) {
        int w = winner[i];
        if (w >= 0) {
            int u = i / G;
            int v = nb[(b0 + u) * KN + w];
            int j = atomicAdd(&cnts[0], 1);
            jOf[i]  = j;
            vehG[j] = v;
        }
    }
    __syncthreads();

    // ---- active positions: any occupied column-neighbor ----
    for (int i = tid; i < U * G; i += 256) {
        int pos = i % G;
        int h   = pos / 3;
        bool a = jOf[i] >= 0;
        if (h > 0)          a |= jOf[i - 3] >= 0;
        if (h < GRID_H - 1) a |= jOf[i + 3] >= 0;
        actFlag[i] = a ? 1 : 0;
        if (a) {
            int s = atomicAdd(&cnts[1], 1);
            actList[s] = i;
        }
    }
    __syncthreads();
    const int tot    = cnts[0];
    const int nAct   = cnts[1];
    const int ntiles = (tot + 31) >> 5;

    // ---- tiles: gather -> conv3x1 -> sparse assembly ----
    for (int t = 0; t < ntiles; ++t) {
        const int  jBase = t << 5;
        const int  nT    = min(32, tot - jBase);
        const bool last  = (t == ntiles - 1);

        for (int i = tid; i < (nT << 7); i += 256) {
            int s = i >> 7, ic = i & 127;
            int v = vehG[jBase + s];
            featC[s * FPITCH + ic] =
                __ldg(enc + (size_t)v * (ENC * TS) + ic * TS + (TS - 1));
        }
        __syncthreads();

        // conv: warp = (ocg, ih). lane = slot. 3 kh-accumulators.
        {
            const int ocg = wid & 3;
            const int ih  = wid >> 2;
            const float*  fr = featC + lan * FPITCH + (ih << 6);
            const float4* w0 = (const float4*)wT + ((ih << 6) << 2) + ocg;
            const float4* w1 = (const float4*)wT + 512 + ((ih << 6) << 2) + ocg;
            const float4* w2 = (const float4*)wT + 1024 + ((ih << 6) << 2) + ocg;
            float4 ac0 = make_float4(0.f, 0.f, 0.f, 0.f);
            float4 ac1 = make_float4(0.f, 0.f, 0.f, 0.f);
            float4 ac2 = make_float4(0.f, 0.f, 0.f, 0.f);
            #pragma unroll 8
            for (int j = 0; j < 64; ++j) {
                float  f  = fr[j];
                float4 v0 = __ldg(w0 + (j << 2));   // uniform across lanes
                float4 v1 = __ldg(w1 + (j << 2));
                float4 v2 = __ldg(w2 + (j << 2));
                ac0.x += f * v0.x; ac0.y += f * v0.y; ac0.z += f * v0.z; ac0.w += f * v0.w;
                ac1.x += f * v1.x; ac1.y += f * v1.y; ac1.z += f * v1.z; ac1.w += f * v1.w;
                ac2.x += f * v2.x; ac2.y += f * v2.y; ac2.z += f * v2.z; ac2.w += f * v2.w;
            }
            if (lan < nT) {
                float4* yb = (float4*)yT + (((ih << 5) + lan) * 3 << 2) + ocg;
                yb[0] = ac0; yb[4] = ac1; yb[8] = ac2;
            }
        }
        __syncthreads();

        // sparse assembly over active positions
        for (int a = tid; a < (nAct << 2); a += 256) {
            int e = actList[a >> 2];
            int g = a & 3;
            int pos = e % G;
            int h   = pos / 3;
            float4 val;
            if (t == 0) val = ((const float4*)b31s)[g];
            else        val = ((float4*)a1)[(e << 2) + g];
            #pragma unroll
            for (int dh = -1; dh <= 1; ++dh) {
                int hh = h + dh;
                if ((unsigned)hh < (unsigned)GRID_H) {
                    int j = jOf[e + dh * 3];
                    int s = j - jBase;
                    if (s >= 0 && s < nT) {
                        int kh = dh + 1;
                        float4 y0 = ((const float4*)yT)[((      s) * 3 + kh) * 4 + g];
                        float4 y1 = ((const float4*)yT)[((32 +  s) * 3 + kh) * 4 + g];
                        val.x += y0.x + y1.x; val.y += y0.y + y1.y;
                        val.z += y0.z + y1.z; val.w += y0.w + y1.w;
                    }
                }
            }
            if (last) {
                val.x = lrelu(val.x); val.y = lrelu(val.y);
                val.z = lrelu(val.z); val.w = lrelu(val.w);
            }
            ((float4*)a1)[(e << 2) + g] = val;
        }
        __syncthreads();
    }

    // ---- conv1x1 + lrelu + 3x3/3 maxpool with c0 shortcut.
    //      warp-task=(u,ph), lane=oc2. p[f][u], f = oc2*5+ph. ----
    float* const p = yT;   // 160*8 floats; yT dead
    {
        float wr[16];
        #pragma unroll
        for (int ic = 0; ic < 16; ++ic) wr[ic] = w11s[(ic << 5) + lan];
        const float bias = b11s[lan];
        const float c0v  = c0s[lan];
        for (int wt = wid; wt < U * 5; wt += 8) {
            int u = wt / 5, ph = wt - u * 5;
            float m = -3.4e38f;
            int h1 = min(3 * ph + 3, GRID_H);
            for (int h = 3 * ph; h < h1; ++h) {
                #pragma unroll
                for (int w = 0; w < 3; ++w) {
                    int e = u * G + h * 3 + w;
                    float s;
                    if (actFlag[e]) {              // uniform across warp
                        const float4* ar = (const float4*)(a1 + (e << 4));
                        float4 q0 = ar[0], q1 = ar[1], q2 = ar[2], q3 = ar[3];
                        s = bias
                            + q0.x * wr[0]  + q0.y * wr[1]  + q0.z * wr[2]  + q0.w * wr[3]
                            + q1.x * wr[4]  + q1.y * wr[5]  + q1.z * wr[6]  + q1.w * wr[7]
                            + q2.x * wr[8]  + q2.y * wr[9]  + q2.z * wr[10] + q2.w * wr[11]
                            + q3.x * wr[12] + q3.y * wr[13] + q3.z * wr[14] + q3.w * wr[15];
                        s = lrelu(s);
                    } else {
                        s = c0v;
                    }
                    m = fmaxf(m, s);
                }
            }
            p[((lan * 5 + ph) << 3) + u] = m;
        }
    }
    __syncthreads();

    // ---- FC 160->64 cooperative: warp=(o-half, f-quarter), 8 batch accumulators ----
    float* const red = featC;                    // red[fq][o][u8]; featC dead
    {
        int orr = wid & 1, fq = wid >> 1;
        int o = (orr << 5) + lan;
        float acc[U];
        #pragma unroll
        for (int u = 0; u < U; ++u) acc[u] = 0.f;
        int f0 = fq * 40;
        #pragma unroll 4
        for (int f = f0; f < f0 + 40; ++f) {
            float  wv = __ldg(fcwT + (f << 6) + o);          // 1 line / warp
            const float4* pv = (const float4*)(p + (f << 3)); // uniform
            float4 pa = pv[0], pb = pv[1];
            acc[0] += wv * pa.x; acc[1] += wv * pa.y;
            acc[2] += wv * pa.z; acc[3] += wv * pa.w;
            acc[4] += wv * pb.x; acc[5] += wv * pb.y;
            acc[6] += wv * pb.z; acc[7] += wv * pb.w;
        }
        float4* rb = (float4*)(red + (((fq << 6) + o) << 3));
        rb[0] = make_float4(acc[0], acc[1], acc[2], acc[3]);
        rb[1] = make_float4(acc[4], acc[5], acc[6], acc[7]);
    }
    __syncthreads();
    for (int t2 = tid; t2 < U * SOCD; t2 += 256) {
        int u = t2 >> 6, o = t2 & 63;
        int b = b0 + u;
        if (b < batch) {
            float acc = __ldg(fcb + o);
            #pragma unroll
            for (int fq = 0; fq < 4; ++fq)
                acc += red[(((fq << 6) + o) << 3) + u];
            out[b * SOCD + o] = lrelu(acc);
        }
    }
}

} // namespace

extern "C" void kernel_launch(void* const* d_in, const int* in_sizes, int n_in,
                              void* d_out, int out_size)
{
    const float* enc = (const float*)d_in[0];
    const int*   nb  = (const int*)  d_in[1];
    const int*   gp  = (const int*)  d_in[2];
    const float* w31 = (const float*)d_in[3];
    const float* b31 = (const float*)d_in[4];
    const float* w11 = (const float*)d_in[5];
    const float* b11 = (const float*)d_in[6];
    const float* fcw = (const float*)d_in[7];
    const float* fcb = (const float*)d_in[8];
    float* out = (float*)d_out;

    const int batch = in_sizes[1] / KN;   // 8192

    cudaFuncSetAttribute(csp_kernel,
                         cudaFuncAttributeMaxDynamicSharedMemorySize, SMEM_BYTES);

    prep_kernel<<<(FCD * SOCD + 255) / 256, 256>>>(w31, fcw, b31, w11, b11);
    csp_kernel<<<(batch + U - 1) / U, 256, SMEM_BYTES>>>(enc, nb, gp, b31, w11, b11,
                                                          fcb, out, batch);
}

// round 14
// speedup vs baseline: 1.5256x; 1.3397x over previous
#include <cuda_runtime.h>

// Round 14: round-12 base + conv weights in SHARED memory.
//  Diagnosis: 44-55KB smem x 4-5 blocks leaves ~8KB L1D, so the conv loop's
//  uniform weight LDGs ran at L2 latency (~234cyc) every iteration. Staging
//  wT into smem (24KB, once per block) turns them into 29-cyc LDS broadcasts.
//  Cost: 68KB dynamic smem -> 3 blocks/SM; evidence says latency >> occupancy here.
namespace {

constexpr int GRID_H = 13;
constexpr int GRID_W = 3;
constexpr int G      = GRID_H * GRID_W;   // 39
constexpr int ENC    = 128;
constexpr int TS     = 16;
constexpr int C31    = 16;
constexpr int C11    = 32;
constexpr int SOCD   = 64;
constexpr int KN     = 32;
constexpr int U      = 4;                 // batches per block
constexpr int FPITCH = 129;
constexpr int MAXJ   = U * KN;
constexpr int FCD    = 160;

// dynamic smem layout (float offsets)
constexpr int OFF_WTS   = 0;                        // 3*128*16 = 6144
constexpr int OFF_FEATC = OFF_WTS + 3 * ENC * C31;  // 4128; later red[4][64][4]
constexpr int OFF_YT    = OFF_FEATC + 32 * FPITCH;  // 3072; later p[160][4]
constexpr int OFF_A1    = OFF_YT + 2 * 32 * 3 * C31;// 2496; winner ints at start
constexpr int OFF_W11S  = OFF_A1 + U * G * C31;     // 512
constexpr int OFF_B31S  = OFF_W11S + C31 * C11;     // 16
constexpr int OFF_B11S  = OFF_B31S + C31;           // 32
constexpr int OFF_C0S   = OFF_B11S + C11;           // 32
constexpr int OFF_INT   = OFF_C0S + C11;
constexpr int NI_JOF    = U * G;                    // 156
constexpr int SMEM_BYTES = (OFF_INT + 3 * NI_JOF + MAXJ + 2) * 4 + 32;

__device__ __align__(16) float wT[3 * ENC * C31];     // [kh][ic][oc16]
__device__ __align__(16) float fcwT[FCD * SOCD];      // [f][o]
__device__ __align__(16) float c0g[C11];              // lrelu(w11.lrelu(b31)+b11)

__device__ __forceinline__ float lrelu(float x) { return x > 0.0f ? x : 0.1f * x; }

__global__ void prep_kernel(const float* __restrict__ w31,
                            const float* __restrict__ fcw,
                            const float* __restrict__ b31,
                            const float* __restrict__ w11,
                            const float* __restrict__ b11)
{
    int i = blockIdx.x * 256 + threadIdx.x;
    if (i < 3 * ENC * C31) {
        int kh = i >> 11;
        int r  = i & 2047;
        int ic = r >> 4, oc = r & 15;
        wT[i] = w31[(oc * ENC + ic) * 3 + kh];
    }
    if (i < FCD * SOCD) {
        int f = i >> 6, o = i & 63;
        fcwT[i] = fcw[o * FCD + f];
    }
    if (i < C11) {
        float s = b11[i];
        for (int ic = 0; ic < C31; ++ic)
            s += w11[i * C31 + ic] * lrelu(b31[ic]);
        c0g[i] = lrelu(s);
    }
}

__global__ __launch_bounds__(256, 3)
void csp_kernel(const float* __restrict__ enc,   // [N_VEH,128,16]
                const int*   __restrict__ nb,    // [B,32]
                const int*   __restrict__ gp,    // [N_VEH,2]
                const float* __restrict__ b31,   // [16]
                const float* __restrict__ w11,   // [32,16]
                const float* __restrict__ b11,   // [32]
                const float* __restrict__ fcb,   // [64]
                float*       __restrict__ out,   // [B,64]
                int batch)
{
    extern __shared__ __align__(16) float sm[];
    float* const wTs   = sm + OFF_WTS;
    float* const featC = sm + OFF_FEATC;
    float* const yT    = sm + OFF_YT;
    float* const a1    = sm + OFF_A1;
    float* const w11s  = sm + OFF_W11S;
    float* const b31s  = sm + OFF_B31S;
    float* const b11s  = sm + OFF_B11S;
    float* const c0s   = sm + OFF_C0S;
    int*   const jOf     = (int*)(sm + OFF_INT);
    int*   const actFlag = jOf + NI_JOF;
    int*   const actList = actFlag + NI_JOF;
    int*   const vehG    = actList + NI_JOF;
    int*   const cnts    = vehG + MAXJ;            // [0]=tot [1]=nAct

    const int b0  = blockIdx.x * U;
    const int tid = threadIdx.x;
    const int wid = tid >> 5;
    const int lan = tid & 31;

    // ---- stage weights into smem (coalesced float4) + small weights / init ----
    {
        const float4* wg  = (const float4*)wT;
        float4*       ws4 = (float4*)wTs;
        #pragma unroll
        for (int i = tid; i < (3 * ENC * C31) / 4; i += 256)
            ws4[i] = wg[i];
    }
    for (int i = tid; i < C31 * C11; i += 256) {
        int ic = i >> 5, oc = i & 31;
        w11s[i] = __ldg(w11 + oc * C31 + ic);
    }
    if (tid < C31) b31s[tid] = __ldg(b31 + tid);
    if (tid < C11) { b11s[tid] = __ldg(b11 + tid); c0s[tid] = c0g[tid]; }
    if (tid < U * G) jOf[tid] = -1;
    if (tid < 2) cnts[tid] = 0;
    int* winner = (int*)a1;                        // a1 region as winner scratch
    if (tid < U * G) winner[tid] = -1;
    __syncthreads();

    // ---- winners per cell ----
    if (tid < U * KN) {
        int u = tid >> 5, k = tid & 31;
        int b = b0 + u;
        if (b < batch) {
            int v = nb[b * KN + k];
            int x = __ldg(gp + 2 * v), yy = __ldg(gp + 2 * v + 1);
            if (x >= 0 && x < GRID_H && yy >= 0 && yy < GRID_W)
                atomicMax(&winner[u * G + x * GRID_W + yy], k);
        }
    }
    __syncthreads();
    if (tid < U * G) {
        int w = winner[tid];
        if (w >= 0) {
            int u = tid / G;
            int v = nb[(b0 + u) * KN + w];
            int j = atomicAdd(&cnts[0], 1);
            jOf[tid]  = j;
            vehG[j] = v;
        }
    }
    __syncthreads();

    // ---- active positions: any occupied column-neighbor ----
    if (tid < U * G) {
        int pos = tid % G;
        int h   = pos / 3;
        bool a = jOf[tid] >= 0;
        if (h > 0)          a |= jOf[tid - 3] >= 0;
        if (h < GRID_H - 1) a |= jOf[tid + 3] >= 0;
        actFlag[tid] = a ? 1 : 0;
        if (a) {
            int s = atomicAdd(&cnts[1], 1);
            actList[s] = tid;
        }
    }
    __syncthreads();
    const int tot    = cnts[0];
    const int nAct   = cnts[1];
    const int ntiles = (tot + 31) >> 5;

    // ---- tiles: gather -> conv3x1 (LDS weights) -> sparse assembly ----
    for (int t = 0; t < ntiles; ++t) {
        const int  jBase = t << 5;
        const int  nT    = min(32, tot - jBase);
        const bool last  = (t == ntiles - 1);

        for (int i = tid; i < (nT << 7); i += 256) {
            int s = i >> 7, ic = i & 127;
            int v = vehG[jBase + s];
            featC[s * FPITCH + ic] =
                __ldg(enc + (size_t)v * (ENC * TS) + ic * TS + (TS - 1));
        }
        __syncthreads();

        // conv: warp = (ocg, ih). lane = slot. 3 kh-accumulators, LDS weights.
        {
            const int ocg = wid & 3;
            const int ih  = wid >> 2;
            const float*  fr = featC + lan * FPITCH + (ih << 6);
            const float4* w0 = (const float4*)wTs + ((ih << 6) << 2) + ocg;          // kh=0
            const float4* w1 = (const float4*)wTs + 512 + ((ih << 6) << 2) + ocg;    // kh=1
            const float4* w2 = (const float4*)wTs + 1024 + ((ih << 6) << 2) + ocg;   // kh=2
            float4 ac0 = make_float4(0.f, 0.f, 0.f, 0.f);
            float4 ac1 = make_float4(0.f, 0.f, 0.f, 0.f);
            float4 ac2 = make_float4(0.f, 0.f, 0.f, 0.f);
            #pragma unroll 8
            for (int j = 0; j < 64; ++j) {
                float  f  = fr[j];
                float4 v0 = w0[j << 2];   // LDS.128 broadcast (29 cyc)
                float4 v1 = w1[j << 2];
                float4 v2 = w2[j << 2];
                ac0.x += f * v0.x; ac0.y += f * v0.y; ac0.z += f * v0.z; ac0.w += f * v0.w;
                ac1.x += f * v1.x; ac1.y += f * v1.y; ac1.z += f * v1.z; ac1.w += f * v1.w;
                ac2.x += f * v2.x; ac2.y += f * v2.y; ac2.z += f * v2.z; ac2.w += f * v2.w;
            }
            if (lan < nT) {
                float4* yb = (float4*)yT + (((ih << 5) + lan) * 3 << 2) + ocg;
                yb[0] = ac0; yb[4] = ac1; yb[8] = ac2;
            }
        }
        __syncthreads();

        // sparse assembly over active positions
        for (int a = tid; a < (nAct << 2); a += 256) {
            int e = actList[a >> 2];
            int g = a & 3;
            int pos = e % G;
            int h   = pos / 3;
            float4 val;
            if (t == 0) val = ((const float4*)b31s)[g];
            else        val = ((float4*)a1)[(e << 2) + g];
            #pragma unroll
            for (int dh = -1; dh <= 1; ++dh) {
                int hh = h + dh;
                if ((unsigned)hh < (unsigned)GRID_H) {
                    int j = jOf[e + dh * 3];
                    int s = j - jBase;
                    if (s >= 0 && s < nT) {
                        int kh = dh + 1;
                        float4 y0 = ((const float4*)yT)[((      s) * 3 + kh) * 4 + g];
                        float4 y1 = ((const float4*)yT)[((32 +  s) * 3 + kh) * 4 + g];
                        val.x += y0.x + y1.x; val.y += y0.y + y1.y;
                        val.z += y0.z + y1.z; val.w += y0.w + y1.w;
                    }
                }
            }
            if (last) {
                val.x = lrelu(val.x); val.y = lrelu(val.y);
                val.z = lrelu(val.z); val.w = lrelu(val.w);
            }
            ((float4*)a1)[(e << 2) + g] = val;
        }
        __syncthreads();
    }

    // ---- conv1x1 + lrelu + 3x3/3 maxpool with c0 shortcut ----
    float* const p = yT;   // p[f][u], f = oc2*5+ph; yT dead
    {
        float wr[16];
        #pragma unroll
        for (int ic = 0; ic < 16; ++ic) wr[ic] = w11s[(ic << 5) + lan];
        const float bias = b11s[lan];
        const float c0v  = c0s[lan];
        for (int wt = wid; wt < U * 5; wt += 8) {
            int u = wt / 5, ph = wt - u * 5;
            float m = -3.4e38f;
            int h1 = min(3 * ph + 3, GRID_H);
            for (int h = 3 * ph; h < h1; ++h) {
                #pragma unroll
                for (int w = 0; w < 3; ++w) {
                    int e = u * G + h * 3 + w;
                    float s;
                    if (actFlag[e]) {              // uniform across warp
                        const float4* ar = (const float4*)(a1 + (e << 4));
                        float4 q0 = ar[0], q1 = ar[1], q2 = ar[2], q3 = ar[3];
                        s = bias
                            + q0.x * wr[0]  + q0.y * wr[1]  + q0.z * wr[2]  + q0.w * wr[3]
                            + q1.x * wr[4]  + q1.y * wr[5]  + q1.z * wr[6]  + q1.w * wr[7]
                            + q2.x * wr[8]  + q2.y * wr[9]  + q2.z * wr[10] + q2.w * wr[11]
                            + q3.x * wr[12] + q3.y * wr[13] + q3.z * wr[14] + q3.w * wr[15];
                        s = lrelu(s);
                    } else {
                        s = c0v;
                    }
                    m = fmaxf(m, s);
                }
            }
            p[((lan * 5 + ph) << 2) + u] = m;
        }
    }
    __syncthreads();

    // ---- FC 160->64 cooperative: warp=(o-half, f-quarter) ----
    float* const red = featC;                    // red[fq][o][u]; featC dead
    {
        int orr = wid & 1, fq = wid >> 1;
        int o = (orr << 5) + lan;
        float a0 = 0.f, s1 = 0.f, a2 = 0.f, a3 = 0.f;
        int f0 = fq * 40;
        #pragma unroll 8
        for (int f = f0; f < f0 + 40; ++f) {
            float  wv = __ldg(fcwT + (f << 6) + o);        // 1 line / warp
            float4 pv = *(const float4*)(p + (f << 2));    // uniform
            a0 += wv * pv.x; s1 += wv * pv.y;
            a2 += wv * pv.z; a3 += wv * pv.w;
        }
        *(float4*)(red + ((fq << 6) + o) * 4) = make_float4(a0, s1, a2, a3);
    }
    __syncthreads();
    {
        int u = tid >> 6, o = tid & 63;
        int b = b0 + u;
        if (b < batch) {
            float acc = __ldg(fcb + o);
            #pragma unroll
            for (int fq = 0; fq < 4; ++fq)
                acc += red[((fq << 6) + o) * 4 + u];
            out[b * SOCD + o] = lrelu(acc);
        }
    }
}

} // namespace

extern "C" void kernel_launch(void* const* d_in, const int* in_sizes, int n_in,
                              void* d_out, int out_size)
{
    const float* enc = (const float*)d_in[0];
    const int*   nb  = (const int*)  d_in[1];
    const int*   gp  = (const int*)  d_in[2];
    const float* w31 = (const float*)d_in[3];
    const float* b31 = (const float*)d_in[4];
    const float* w11 = (const float*)d_in[5];
    const float* b11 = (const float*)d_in[6];
    const float* fcw = (const float*)d_in[7];
    const float* fcb = (const float*)d_in[8];
    float* out = (float*)d_out;

    const int batch = in_sizes[1] / KN;   // 8192

    cudaFuncSetAttribute(csp_kernel,
                         cudaFuncAttributeMaxDynamicSharedMemorySize, SMEM_BYTES);

    prep_kernel<<<(FCD * SOCD + 255) / 256, 256>>>(w31, fcw, b31, w11, b11);
    csp_kernel<<<(batch + U - 1) / U, 256, SMEM_BYTES>>>(enc, nb, gp, b31, w11, b11,
                                                          fcb, out, batch);
}

// round 15
// speedup vs baseline: 1.5534x; 1.0183x over previous
#include <cuda_runtime.h>

// Round 15: round-14 base + packed f32x2 FMA in the conv inner loop.
//  - fma.rn.f32x2 (FFMA2, sm_100+ PTX): 12 FFMA -> 6 FFMA2 + 1 pack per j.
//    Bitwise-identical per-lane .rn arithmetic; conv instr count -31%.
//  - everything else identical to round 14 (121.3us).
namespace {

constexpr int GRID_H = 13;
constexpr int GRID_W = 3;
constexpr int G      = GRID_H * GRID_W;   // 39
constexpr int ENC    = 128;
constexpr int TS     = 16;
constexpr int C31    = 16;
constexpr int C11    = 32;
constexpr int SOCD   = 64;
constexpr int KN     = 32;
constexpr int U      = 4;                 // batches per block
constexpr int FPITCH = 129;
constexpr int MAXJ   = U * KN;
constexpr int FCD    = 160;

// dynamic smem layout (float offsets)
constexpr int OFF_WTS   = 0;                        // 3*128*16 = 6144
constexpr int OFF_FEATC = OFF_WTS + 3 * ENC * C31;  // 4128; later red[4][64][4]
constexpr int OFF_YT    = OFF_FEATC + 32 * FPITCH;  // 3072; later p[160][4]
constexpr int OFF_A1    = OFF_YT + 2 * 32 * 3 * C31;// 2496; winner ints at start
constexpr int OFF_W11S  = OFF_A1 + U * G * C31;     // 512
constexpr int OFF_B31S  = OFF_W11S + C31 * C11;     // 16
constexpr int OFF_B11S  = OFF_B31S + C31;           // 32
constexpr int OFF_C0S   = OFF_B11S + C11;           // 32
constexpr int OFF_INT   = OFF_C0S + C11;
constexpr int NI_JOF    = U * G;                    // 156
constexpr int SMEM_BYTES = (OFF_INT + 3 * NI_JOF + MAXJ + 2) * 4 + 32;

__device__ __align__(16) float wT[3 * ENC * C31];     // [kh][ic][oc16]
__device__ __align__(16) float fcwT[FCD * SOCD];      // [f][o]
__device__ __align__(16) float c0g[C11];              // lrelu(w11.lrelu(b31)+b11)

__device__ __forceinline__ float lrelu(float x) { return x > 0.0f ? x : 0.1f * x; }

__device__ __forceinline__ unsigned long long pack2(float f) {
    unsigned long long r;
    asm("mov.b64 %0, {%1, %1};" : "=l"(r) : "f"(f));
    return r;
}
__device__ __forceinline__ void ffma2(unsigned long long& d,
                                      unsigned long long a,
                                      unsigned long long b) {
    asm("fma.rn.f32x2 %0, %1, %2, %0;" : "+l"(d) : "l"(a), "l"(b));
}

__global__ void prep_kernel(const float* __restrict__ w31,
                            const float* __restrict__ fcw,
                            const float* __restrict__ b31,
                            const float* __restrict__ w11,
                            const float* __restrict__ b11)
{
    int i = blockIdx.x * 256 + threadIdx.x;
    if (i < 3 * ENC * C31) {
        int kh = i >> 11;
        int r  = i & 2047;
        int ic = r >> 4, oc = r & 15;
        wT[i] = w31[(oc * ENC + ic) * 3 + kh];
    }
    if (i < FCD * SOCD) {
        int f = i >> 6, o = i & 63;
        fcwT[i] = fcw[o * FCD + f];
    }
    if (i < C11) {
        float s = b11[i];
        for (int ic = 0; ic < C31; ++ic)
            s += w11[i * C31 + ic] * lrelu(b31[ic]);
        c0g[i] = lrelu(s);
    }
}

__global__ __launch_bounds__(256, 3)
void csp_kernel(const float* __restrict__ enc,   // [N_VEH,128,16]
                const int*   __restrict__ nb,    // [B,32]
                const int*   __restrict__ gp,    // [N_VEH,2]
                const float* __restrict__ b31,   // [16]
                const float* __restrict__ w11,   // [32,16]
                const float* __restrict__ b11,   // [32]
                const float* __restrict__ fcb,   // [64]
                float*       __restrict__ out,   // [B,64]
                int batch)
{
    extern __shared__ __align__(16) float sm[];
    float* const wTs   = sm + OFF_WTS;
    float* const featC = sm + OFF_FEATC;
    float* const yT    = sm + OFF_YT;
    float* const a1    = sm + OFF_A1;
    float* const w11s  = sm + OFF_W11S;
    float* const b31s  = sm + OFF_B31S;
    float* const b11s  = sm + OFF_B11S;
    float* const c0s   = sm + OFF_C0S;
    int*   const jOf     = (int*)(sm + OFF_INT);
    int*   const actFlag = jOf + NI_JOF;
    int*   const actList = actFlag + NI_JOF;
    int*   const vehG    = actList + NI_JOF;
    int*   const cnts    = vehG + MAXJ;            // [0]=tot [1]=nAct

    const int b0  = blockIdx.x * U;
    const int tid = threadIdx.x;
    const int wid = tid >> 5;
    const int lan = tid & 31;

    // ---- stage weights into smem (coalesced float4) + small weights / init ----
    {
        const float4* wg  = (const float4*)wT;
        float4*       ws4 = (float4*)wTs;
        #pragma unroll
        for (int i = tid; i < (3 * ENC * C31) / 4; i += 256)
            ws4[i] = wg[i];
    }
    for (int i = tid; i < C31 * C11; i += 256) {
        int ic = i >> 5, oc = i & 31;
        w11s[i] = __ldg(w11 + oc * C31 + ic);
    }
    if (tid < C31) b31s[tid] = __ldg(b31 + tid);
    if (tid < C11) { b11s[tid] = __ldg(b11 + tid); c0s[tid] = c0g[tid]; }
    if (tid < U * G) jOf[tid] = -1;
    if (tid < 2) cnts[tid] = 0;
    int* winner = (int*)a1;                        // a1 region as winner scratch
    if (tid < U * G) winner[tid] = -1;
    __syncthreads();

    // ---- winners per cell ----
    if (tid < U * KN) {
        int u = tid >> 5, k = tid & 31;
        int b = b0 + u;
        if (b < batch) {
            int v = nb[b * KN + k];
            int x = __ldg(gp + 2 * v), yy = __ldg(gp + 2 * v + 1);
            if (x >= 0 && x < GRID_H && yy >= 0 && yy < GRID_W)
                atomicMax(&winner[u * G + x * GRID_W + yy], k);
        }
    }
    __syncthreads();
    if (tid < U * G) {
        int w = winner[tid];
        if (w >= 0) {
            int u = tid / G;
            int v = nb[(b0 + u) * KN + w];
            int j = atomicAdd(&cnts[0], 1);
            jOf[tid]  = j;
            vehG[j] = v;
        }
    }
    __syncthreads();

    // ---- active positions: any occupied column-neighbor ----
    if (tid < U * G) {
        int pos = tid % G;
        int h   = pos / 3;
        bool a = jOf[tid] >= 0;
        if (h > 0)          a |= jOf[tid - 3] >= 0;
        if (h < GRID_H - 1) a |= jOf[tid + 3] >= 0;
        actFlag[tid] = a ? 1 : 0;
        if (a) {
            int s = atomicAdd(&cnts[1], 1);
            actList[s] = tid;
        }
    }
    __syncthreads();
    const int tot    = cnts[0];
    const int nAct   = cnts[1];
    const int ntiles = (tot + 31) >> 5;

    // ---- tiles: gather -> conv3x1 (LDS weights, f32x2 FMA) -> sparse assembly ----
    for (int t = 0; t < ntiles; ++t) {
        const int  jBase = t << 5;
        const int  nT    = min(32, tot - jBase);
        const bool last  = (t == ntiles - 1);

        for (int i = tid; i < (nT << 7); i += 256) {
            int s = i >> 7, ic = i & 127;
            int v = vehG[jBase + s];
            featC[s * FPITCH + ic] =
                __ldg(enc + (size_t)v * (ENC * TS) + ic * TS + (TS - 1));
        }
        __syncthreads();

        // conv: warp = (ocg, ih). lane = slot. packed f32x2 accumulators.
        {
            const int ocg = wid & 3;
            const int ih  = wid >> 2;
            const float* fr = featC + lan * FPITCH + (ih << 6);
            const ulonglong2* w0 = (const ulonglong2*)wTs + ((ih << 6) << 2) + ocg;
            const ulonglong2* w1 = (const ulonglong2*)wTs + 512 + ((ih << 6) << 2) + ocg;
            const ulonglong2* w2 = (const ulonglong2*)wTs + 1024 + ((ih << 6) << 2) + ocg;
            unsigned long long d00 = 0ull, d01 = 0ull;   // kh0: (x,y),(z,w)
            unsigned long long d10 = 0ull, d11 = 0ull;   // kh1
            unsigned long long d20 = 0ull, d21 = 0ull;   // kh2
            #pragma unroll 8
            for (int j = 0; j < 64; ++j) {
                unsigned long long ff = pack2(fr[j]);
                ulonglong2 v0 = w0[j << 2];   // LDS.128 broadcast
                ulonglong2 v1 = w1[j << 2];
                ulonglong2 v2 = w2[j << 2];
                ffma2(d00, ff, v0.x); ffma2(d01, ff, v0.y);
                ffma2(d10, ff, v1.x); ffma2(d11, ff, v1.y);
                ffma2(d20, ff, v2.x); ffma2(d21, ff, v2.y);
            }
            if (lan < nT) {
                ulonglong2* yb = (ulonglong2*)yT + (((ih << 5) + lan) * 3 << 2) + ocg;
                yb[0] = make_ulonglong2(d00, d01);
                yb[4] = make_ulonglong2(d10, d11);
                yb[8] = make_ulonglong2(d20, d21);
            }
        }
        __syncthreads();

        // sparse assembly over active positions
        for (int a = tid; a < (nAct << 2); a += 256) {
            int e = actList[a >> 2];
            int g = a & 3;
            int pos = e % G;
            int h   = pos / 3;
            float4 val;
            if (t == 0) val = ((const float4*)b31s)[g];
            else        val = ((float4*)a1)[(e << 2) + g];
            #pragma unroll
            for (int dh = -1; dh <= 1; ++dh) {
                int hh = h + dh;
                if ((unsigned)hh < (unsigned)GRID_H) {
                    int j = jOf[e + dh * 3];
                    int s = j - jBase;
                    if (s >= 0 && s < nT) {
                        int kh = dh + 1;
                        float4 y0 = ((const float4*)yT)[((      s) * 3 + kh) * 4 + g];
                        float4 y1 = ((const float4*)yT)[((32 +  s) * 3 + kh) * 4 + g];
                        val.x += y0.x + y1.x; val.y += y0.y + y1.y;
                        val.z += y0.z + y1.z; val.w += y0.w + y1.w;
                    }
                }
            }
            if (last) {
                val.x = lrelu(val.x); val.y = lrelu(val.y);
                val.z = lrelu(val.z); val.w = lrelu(val.w);
            }
            ((float4*)a1)[(e << 2) + g] = val;
        }
        __syncthreads();
    }

    // ---- conv1x1 + lrelu + 3x3/3 maxpool with c0 shortcut ----
    float* const p = yT;   // p[f][u], f = oc2*5+ph; yT dead
    {
        float wr[16];
        #pragma unroll
        for (int ic = 0; ic < 16; ++ic) wr[ic] = w11s[(ic << 5) + lan];
        const float bias = b11s[lan];
        const float c0v  = c0s[lan];
        for (int wt = wid; wt < U * 5; wt += 8) {
            int u = wt / 5, ph = wt - u * 5;
            float m = -3.4e38f;
            int h1 = min(3 * ph + 3, GRID_H);
            for (int h = 3 * ph; h < h1; ++h) {
                #pragma unroll
                for (int w = 0; w < 3; ++w) {
                    int e = u * G + h * 3 + w;
                    float s;
                    if (actFlag[e]) {              // uniform across warp
                        const float4* ar = (const float4*)(a1 + (e << 4));
                        float4 q0 = ar[0], q1 = ar[1], q2 = ar[2], q3 = ar[3];
                        s = bias
                            + q0.x * wr[0]  + q0.y * wr[1]  + q0.z * wr[2]  + q0.w * wr[3]
                            + q1.x * wr[4]  + q1.y * wr[5]  + q1.z * wr[6]  + q1.w * wr[7]
                            + q2.x * wr[8]  + q2.y * wr[9]  + q2.z * wr[10] + q2.w * wr[11]
                            + q3.x * wr[12] + q3.y * wr[13] + q3.z * wr[14] + q3.w * wr[15];
                        s = lrelu(s);
                    } else {
                        s = c0v;
                    }
                    m = fmaxf(m, s);
                }
            }
            p[((lan * 5 + ph) << 2) + u] = m;
        }
    }
    __syncthreads();

    // ---- FC 160->64 cooperative: warp=(o-half, f-quarter) ----
    float* const red = featC;                    // red[fq][o][u]; featC dead
    {
        int orr = wid & 1, fq = wid >> 1;
        int o = (orr << 5) + lan;
        float a0 = 0.f, s1 = 0.f, a2 = 0.f, a3 = 0.f;
        int f0 = fq * 40;
        #pragma unroll 8
        for (int f = f0; f < f0 + 40; ++f) {
            float  wv = __ldg(fcwT + (f << 6) + o);        // 1 line / warp
            float4 pv = *(const float4*)(p + (f << 2));    // uniform
            a0 += wv * pv.x; s1 += wv * pv.y;
            a2 += wv * pv.z; a3 += wv * pv.w;
        }
        *(float4*)(red + ((fq << 6) + o) * 4) = make_float4(a0, s1, a2, a3);
    }
    __syncthreads();
    {
        int u = tid >> 6, o = tid & 63;
        int b = b0 + u;
        if (b < batch) {
            float acc = __ldg(fcb + o);
            #pragma unroll
            for (int fq = 0; fq < 4; ++fq)
                acc += red[((fq << 6) + o) * 4 + u];
            out[b * SOCD + o] = lrelu(acc);
        }
    }
}

} // namespace

extern "C" void kernel_launch(void* const* d_in, const int* in_sizes, int n_in,
                              void* d_out, int out_size)
{
    const float* enc = (const float*)d_in[0];
    const int*   nb  = (const int*)  d_in[1];
    const int*   gp  = (const int*)  d_in[2];
    const float* w31 = (const float*)d_in[3];
    const float* b31 = (const float*)d_in[4];
    const float* w11 = (const float*)d_in[5];
    const float* b11 = (const float*)d_in[6];
    const float* fcw = (const float*)d_in[7];
    const float* fcb = (const float*)d_in[8];
    float* out = (float*)d_out;

    const int batch = in_sizes[1] / KN;   // 8192

    cudaFuncSetAttribute(csp_kernel,
                         cudaFuncAttributeMaxDynamicSharedMemorySize, SMEM_BYTES);

    prep_kernel<<<(FCD * SOCD + 255) / 256, 256>>>(w31, fcw, b31, w11, b11);
    csp_kernel<<<(batch + U - 1) / U, 256, SMEM_BYTES>>>(enc, nb, gp, b31, w11, b11,
                                                          fcb, out, batch);
}